// round 4
// baseline (speedup 1.0000x reference)
#include <cuda_runtime.h>
#include <cuda_bf16.h>
#include <cstdint>

#define BATCH 4
#define CIN   128
#define COUT  256
#define HW    1024
#define TILE_O 64
#define TILE_P 64
#define KEFF   256      // sign-split effective K
#define THREADS 256

// smem layout (bytes). Strides are 16B-multiples with (stride/4 mod 32) == 4
// so ldmatrix row addresses walk 4 banks per row -> conflict-free.
#define A_STRIDE 528    // 256 halves data + 8 halves pad
#define B_STRIDE 144    // 64 halves data + 8 halves pad
#define SMEM_A   0
#define SMEM_B   (TILE_O * A_STRIDE)              // 33792
#define SMEM_TOTAL (SMEM_B + KEFF * B_STRIDE)     // 70656

__device__ __forceinline__ uint32_t smem_u32(const void* p) {
    uint32_t a;
    asm("{ .reg .u64 t; cvta.to.shared.u64 t, %1; cvt.u32.u64 %0, t; }" : "=r"(a) : "l"(p));
    return a;
}
__device__ __forceinline__ uint32_t pack_bf16x2(float lo, float hi) {
    uint32_t r;
    asm("cvt.rn.bf16x2.f32 %0, %1, %2;" : "=r"(r) : "f"(hi), "f"(lo));
    return r;
}
__device__ __forceinline__ void sts64(uint32_t addr, uint32_t a, uint32_t b) {
    asm volatile("st.shared.v2.b32 [%0], {%1,%2};" :: "r"(addr), "r"(a), "r"(b) : "memory");
}
__device__ __forceinline__ void sts128(uint32_t addr, uint4 v) {
    asm volatile("st.shared.v4.b32 [%0], {%1,%2,%3,%4};"
                 :: "r"(addr), "r"(v.x), "r"(v.y), "r"(v.z), "r"(v.w) : "memory");
}
__device__ __forceinline__ void ldsm_x4(uint32_t addr, uint32_t* r) {
    asm volatile("ldmatrix.sync.aligned.m8n8.x4.shared.b16 {%0,%1,%2,%3}, [%4];"
                 : "=r"(r[0]), "=r"(r[1]), "=r"(r[2]), "=r"(r[3]) : "r"(addr));
}
__device__ __forceinline__ void ldsm_x4_trans(uint32_t addr, uint32_t* r) {
    asm volatile("ldmatrix.sync.aligned.m8n8.x4.trans.shared.b16 {%0,%1,%2,%3}, [%4];"
                 : "=r"(r[0]), "=r"(r[1]), "=r"(r[2]), "=r"(r[3]) : "r"(addr));
}
__device__ __forceinline__ void mma_16816(float* c, const uint32_t* a, const uint32_t* b) {
    asm volatile(
        "mma.sync.aligned.m16n8k16.row.col.f32.bf16.bf16.f32 "
        "{%0,%1,%2,%3}, {%4,%5,%6,%7}, {%8,%9}, {%0,%1,%2,%3};"
        : "+f"(c[0]), "+f"(c[1]), "+f"(c[2]), "+f"(c[3])
        : "r"(a[0]), "r"(a[1]), "r"(a[2]), "r"(a[3]), "r"(b[0]), "r"(b[1]));
}

__global__ __launch_bounds__(THREADS, 2)
void pw_relu_mma_kernel(const float* __restrict__ x,
                        const float* __restrict__ w,
                        float* __restrict__ out) {
    extern __shared__ char smem[];
    const uint32_t sb = smem_u32(smem);
    const int tid  = threadIdx.x;
    const int lane = tid & 31;
    const int wid  = tid >> 5;
    const int b  = blockIdx.z;
    const int o0 = blockIdx.y * TILE_O;
    const int p0 = blockIdx.x * TILE_P;

    // ---- front-loaded global reads: 8 float4 of X + 8 float4 of W (MLP=16) ----
    const int pf = tid & 15;               // p = 4*pf .. 4*pf+3
    const int i0 = tid >> 4;               // 0..15
    const float* xb = x + (size_t)b * CIN * HW + p0 + pf * 4;
    const int iv = tid & 31;               // i = 4*iv
    const int oo = tid >> 5;               // 0..7
    const float* wb = w + (size_t)(o0 + oo) * CIN + iv * 4;

    float4 xv[8], wv[8];
#pragma unroll
    for (int it = 0; it < 8; it++)
        xv[it] = *(const float4*)(xb + (size_t)(i0 + it * 16) * HW);
#pragma unroll
    for (int it = 0; it < 8; it++)
        wv[it] = *(const float4*)(wb + (size_t)(it * 8) * CIN);

    // ---- stage X: [eff-k][p] rows; pair rows 2i (relu+), 2i+1 (relu-) ----
#pragma unroll
    for (int it = 0; it < 8; it++) {
        const int i = i0 + it * 16;
        float4 v = xv[it];
        uint32_t pp0 = pack_bf16x2(fmaxf(v.x, 0.f), fmaxf(v.y, 0.f));
        uint32_t pp1 = pack_bf16x2(fmaxf(v.z, 0.f), fmaxf(v.w, 0.f));
        uint32_t pm0 = pack_bf16x2(fmaxf(-v.x, 0.f), fmaxf(-v.y, 0.f));
        uint32_t pm1 = pack_bf16x2(fmaxf(-v.z, 0.f), fmaxf(-v.w, 0.f));
        const uint32_t base = sb + SMEM_B + (uint32_t)(2 * i) * B_STRIDE + pf * 8;
        sts64(base, pp0, pp1);
        sts64(base + B_STRIDE, pm0, pm1);
    }
    // ---- stage W: A rows [o][eff-k], sign pairs contiguous in k ----
#pragma unroll
    for (int it = 0; it < 8; it++) {
        const int o = oo + it * 8;
        float4 v = wv[it];
        uint4 u;
        u.x = pack_bf16x2(fmaxf(v.x, 0.f), fmaxf(-v.x, 0.f));
        u.y = pack_bf16x2(fmaxf(v.y, 0.f), fmaxf(-v.y, 0.f));
        u.z = pack_bf16x2(fmaxf(v.z, 0.f), fmaxf(-v.z, 0.f));
        u.w = pack_bf16x2(fmaxf(v.w, 0.f), fmaxf(-v.w, 0.f));
        sts128(sb + SMEM_A + (uint32_t)o * A_STRIDE + iv * 16, u);
    }
    __syncthreads();

    // ---- mma mainloop: warp tile 16(o) x 32(p); 4x2 warp grid ----
    const int warp_m = wid & 3;    // 4 -> 64 o
    const int warp_n = wid >> 2;   // 2 -> 64 p
    const uint32_t aAddr0 = sb + SMEM_A + (uint32_t)(warp_m * 16 + (lane & 15)) * A_STRIDE
                            + (uint32_t)(lane >> 4) * 16;
    // B x4-trans: lanes 0-15 k-rows at n, lanes 16-31 k-rows at n+8
    const uint32_t bAddr0 = sb + SMEM_B + (uint32_t)(lane & 15) * B_STRIDE
                            + (uint32_t)(warp_n * 32) * 2 + (uint32_t)(lane >> 4) * 16;

    float acc[4][4];
#pragma unroll
    for (int ns = 0; ns < 4; ns++)
#pragma unroll
        for (int j = 0; j < 4; j++) acc[ns][j] = 0.f;

#pragma unroll
    for (int kk = 0; kk < KEFF / 16; kk++) {
        uint32_t a[4];
        ldsm_x4(aAddr0 + kk * 32, a);
        uint32_t bf[2][4];     // [n16 group][fragments: n0-7 pair, n8-15 pair]
        ldsm_x4_trans(bAddr0 + (uint32_t)kk * (16 * B_STRIDE), bf[0]);
        ldsm_x4_trans(bAddr0 + (uint32_t)kk * (16 * B_STRIDE) + 32, bf[1]);
        mma_16816(acc[0], a, &bf[0][0]);
        mma_16816(acc[1], a, &bf[0][2]);
        mma_16816(acc[2], a, &bf[1][0]);
        mma_16816(acc[3], a, &bf[1][2]);
    }

    // ---- epilogue: direct coalesced float2 stores from mma fragments ----
    const int r  = lane >> 2;
    const int c2 = (lane & 3) * 2;
    float* ob = out + ((size_t)b * COUT + o0 + warp_m * 16) * HW + p0 + warp_n * 32 + c2;
#pragma unroll
    for (int ns = 0; ns < 4; ns++) {
        *(float2*)(ob + (size_t)r * HW + ns * 8)       = make_float2(acc[ns][0], acc[ns][1]);
        *(float2*)(ob + (size_t)(r + 8) * HW + ns * 8) = make_float2(acc[ns][2], acc[ns][3]);
    }
}

extern "C" void kernel_launch(void* const* d_in, const int* in_sizes, int n_in,
                              void* d_out, int out_size) {
    const float* x = (const float*)d_in[0];   // (4,128,32,32)
    const float* w = (const float*)d_in[1];   // (256*128,1,1,1)
    float* out = (float*)d_out;               // (4,256,32,32)
    static bool attr_set = false;
    if (!attr_set) {
        cudaFuncSetAttribute(pw_relu_mma_kernel,
                             cudaFuncAttributeMaxDynamicSharedMemorySize, SMEM_TOTAL);
        attr_set = true;
    }
    dim3 grid(HW / TILE_P, COUT / TILE_O, BATCH);   // (16, 4, 4) = 256 CTAs
    pw_relu_mma_kernel<<<grid, THREADS, SMEM_TOTAL>>>(x, w, out);
}

// round 7
// speedup vs baseline: 1.0654x; 1.0654x over previous
#include <cuda_runtime.h>
#include <cuda_bf16.h>
#include <cstdint>

#define BATCH 4
#define CIN   128
#define COUT  256
#define HW    1024
#define TILE_O 32
#define TILE_P 64
#define THREADS 128

// smem (bytes): strides are 16B multiples with (stride/4 mod 32)==4 -> ldmatrix
// row addresses walk 4 banks per row, conflict-free per 8-row phase.
#define A_STRIDE 272            // 128 halves + 8 pad
#define B_STRIDE 144            // 64 halves + 8 pad
#define SMEM_AP  0
#define SMEM_AM  (TILE_O * A_STRIDE)              // 8704
#define SMEM_B   (2 * TILE_O * A_STRIDE)          // 17408
#define SMEM_TOTAL (SMEM_B + CIN * B_STRIDE)      // 35840 (<48KB, no opt-in needed)

__device__ __forceinline__ uint32_t smem_u32(const void* p) {
    uint32_t a;
    asm("{ .reg .u64 t; cvta.to.shared.u64 t, %1; cvt.u32.u64 %0, t; }" : "=r"(a) : "l"(p));
    return a;
}
__device__ __forceinline__ uint32_t pack_bf16x2(float lo, float hi) {
    uint32_t r;
    asm("cvt.rn.bf16x2.f32 %0, %1, %2;" : "=r"(r) : "f"(hi), "f"(lo));
    return r;
}
__device__ __forceinline__ uint32_t relu2(uint32_t v) {          // max.bf16x2(v, +0)
    uint32_t r;
    asm("max.bf16x2 %0, %1, %2;" : "=r"(r) : "r"(v), "r"(0u));
    return r;
}
__device__ __forceinline__ void sts64(uint32_t addr, uint32_t a, uint32_t b) {
    asm volatile("st.shared.v2.b32 [%0], {%1,%2};" :: "r"(addr), "r"(a), "r"(b) : "memory");
}
__device__ __forceinline__ void ldsm_x4(uint32_t addr, uint32_t* r) {
    asm volatile("ldmatrix.sync.aligned.m8n8.x4.shared.b16 {%0,%1,%2,%3}, [%4];"
                 : "=r"(r[0]), "=r"(r[1]), "=r"(r[2]), "=r"(r[3]) : "r"(addr));
}
__device__ __forceinline__ void ldsm_x4_trans(uint32_t addr, uint32_t* r) {
    asm volatile("ldmatrix.sync.aligned.m8n8.x4.trans.shared.b16 {%0,%1,%2,%3}, [%4];"
                 : "=r"(r[0]), "=r"(r[1]), "=r"(r[2]), "=r"(r[3]) : "r"(addr));
}
__device__ __forceinline__ void mma_16816(float* c, const uint32_t* a, const uint32_t* b) {
    asm volatile(
        "mma.sync.aligned.m16n8k16.row.col.f32.bf16.bf16.f32 "
        "{%0,%1,%2,%3}, {%4,%5,%6,%7}, {%8,%9}, {%0,%1,%2,%3};"
        : "+f"(c[0]), "+f"(c[1]), "+f"(c[2]), "+f"(c[3])
        : "r"(a[0]), "r"(a[1]), "r"(a[2]), "r"(a[3]), "r"(b[0]), "r"(b[1]));
}

__global__ __launch_bounds__(THREADS, 4)
void pw_relu_mma_kernel(const float* __restrict__ x,
                        const float* __restrict__ w,
                        float* __restrict__ out) {
    extern __shared__ char smem[];
    const uint32_t sb = smem_u32(smem);
    const int tid  = threadIdx.x;
    const int lane = tid & 31;
    const int wid  = tid >> 5;
    const int b  = blockIdx.z;
    const int o0 = blockIdx.y * TILE_O;
    const int p0 = blockIdx.x * TILE_P;

    // ---- X mapping: thread covers rows {i0+16it} ∪ {i0+8+16it}, col p=4*pf ----
    const int pf = tid & 15;
    const int i0 = tid >> 4;               // 0..7
    const float* xb = x + (size_t)b * CIN * HW + p0 + pf * 4;
    // ---- W mapping: rows o = oo+4it, cols i = 4*iv ----
    const int iv = tid & 31;
    const int oo = tid >> 5;               // 0..3
    const float* wb = w + (size_t)(o0 + oo) * CIN + iv * 4;

    // front-loaded global reads
    float4 xv0[8], xv1[8], wv[8];
#pragma unroll
    for (int it = 0; it < 8; it++)
        xv0[it] = *(const float4*)(xb + (size_t)(i0 + it * 16) * HW);
#pragma unroll
    for (int it = 0; it < 8; it++)
        xv1[it] = *(const float4*)(xb + (size_t)(i0 + 8 + it * 16) * HW);
#pragma unroll
    for (int it = 0; it < 8; it++)
        wv[it] = *(const float4*)(wb + (size_t)(it * 4) * CIN);

    // ---- stage W as A+ / A- tiles [o][k], K-major ----
#pragma unroll
    for (int it = 0; it < 8; it++) {
        const int o = oo + it * 4;
        float4 v = wv[it];
        uint32_t pr0 = pack_bf16x2(fmaxf(v.x, 0.f), fmaxf(v.y, 0.f));
        uint32_t pr1 = pack_bf16x2(fmaxf(v.z, 0.f), fmaxf(v.w, 0.f));
        uint32_t mr0 = pack_bf16x2(fmaxf(-v.x, 0.f), fmaxf(-v.y, 0.f));
        uint32_t mr1 = pack_bf16x2(fmaxf(-v.z, 0.f), fmaxf(-v.w, 0.f));
        sts64(sb + SMEM_AP + (uint32_t)o * A_STRIDE + iv * 8, pr0, pr1);
        sts64(sb + SMEM_AM + (uint32_t)o * A_STRIDE + iv * 8, mr0, mr1);
    }
    // ---- stage X as plain bf16 [k=i][p] (sign split happens in registers) ----
#pragma unroll
    for (int it = 0; it < 8; it++) {
        const int i = i0 + it * 16;
        float4 v = xv0[it];
        sts64(sb + SMEM_B + (uint32_t)i * B_STRIDE + pf * 8,
              pack_bf16x2(v.x, v.y), pack_bf16x2(v.z, v.w));
    }
#pragma unroll
    for (int it = 0; it < 8; it++) {
        const int i = i0 + 8 + it * 16;
        float4 v = xv1[it];
        sts64(sb + SMEM_B + (uint32_t)i * B_STRIDE + pf * 8,
              pack_bf16x2(v.x, v.y), pack_bf16x2(v.z, v.w));
    }
    __syncthreads();

    // ---- mainloop: warp grid 2(m) x 2(n), warp tile 16(o) x 32(p), 8 k16-iters ----
    const int warp_m = wid & 1;
    const int warp_n = wid >> 1;
    const uint32_t aAddrP = sb + SMEM_AP + (uint32_t)(warp_m * 16 + (lane & 15)) * A_STRIDE
                            + (uint32_t)(lane >> 4) * 16;
    const uint32_t aAddrM = aAddrP + (SMEM_AM - SMEM_AP);
    const uint32_t bAddr0 = sb + SMEM_B + (uint32_t)(lane & 15) * B_STRIDE
                            + (uint32_t)(warp_n * 32) * 2 + (uint32_t)(lane >> 4) * 16;

    float acc[4][4];
#pragma unroll
    for (int ns = 0; ns < 4; ns++)
#pragma unroll
        for (int j = 0; j < 4; j++) acc[ns][j] = 0.f;

#pragma unroll
    for (int kk = 0; kk < CIN / 16; kk++) {
        uint32_t ap[4], am[4];
        ldsm_x4(aAddrP + kk * 32, ap);
        ldsm_x4(aAddrM + kk * 32, am);
        uint32_t bx[2][4];
        ldsm_x4_trans(bAddr0 + (uint32_t)kk * (16 * B_STRIDE), bx[0]);
        ldsm_x4_trans(bAddr0 + (uint32_t)kk * (16 * B_STRIDE) + 32, bx[1]);
        uint32_t xp[2][4], xm[2][4];
#pragma unroll
        for (int g = 0; g < 2; g++)
#pragma unroll
            for (int j = 0; j < 4; j++) {
                xp[g][j] = relu2(bx[g][j]);
                xm[g][j] = relu2(bx[g][j] ^ 0x80008000u);
            }
        mma_16816(acc[0], ap, &xp[0][0]);
        mma_16816(acc[1], ap, &xp[0][2]);
        mma_16816(acc[2], ap, &xp[1][0]);
        mma_16816(acc[3], ap, &xp[1][2]);
        mma_16816(acc[0], am, &xm[0][0]);
        mma_16816(acc[1], am, &xm[0][2]);
        mma_16816(acc[2], am, &xm[1][0]);
        mma_16816(acc[3], am, &xm[1][2]);
    }

    // ---- epilogue: direct coalesced float2 stores from mma fragments ----
    const int r  = lane >> 2;
    const int c2 = (lane & 3) * 2;
    float* ob = out + ((size_t)b * COUT + o0 + warp_m * 16) * HW + p0 + warp_n * 32 + c2;
#pragma unroll
    for (int ns = 0; ns < 4; ns++) {
        *(float2*)(ob + (size_t)r * HW + ns * 8)       = make_float2(acc[ns][0], acc[ns][1]);
        *(float2*)(ob + (size_t)(r + 8) * HW + ns * 8) = make_float2(acc[ns][2], acc[ns][3]);
    }
}

extern "C" void kernel_launch(void* const* d_in, const int* in_sizes, int n_in,
                              void* d_out, int out_size) {
    const float* x = (const float*)d_in[0];   // (4,128,32,32)
    const float* w = (const float*)d_in[1];   // (256*128,1,1,1)
    float* out = (float*)d_out;               // (4,256,32,32)
    dim3 grid(HW / TILE_P, COUT / TILE_O, BATCH);   // (16, 8, 4) = 512 CTAs
    pw_relu_mma_kernel<<<grid, THREADS, SMEM_TOTAL>>>(x, w, out);
}